// round 12
// baseline (speedup 1.0000x reference)
#include <cuda_runtime.h>
#include <cuda_bf16.h>
#include <cstdint>

// AdaptiveEmbedding: 3-cluster gather+projection.
// detect -> classify (warp-aggregated) -> conv_all (grid-stride bf16 hi/lo
// pre-split) -> z-grid cp.async 3-stage pipelined mma.sync GEMM (2 CTAs/SM).
// R12: MMA step-reordering (hh/hl/lh passes) to break accumulator RAW chains.
// Baseline-PTX only (harness targets sm_103, no 'a': no tcgen05).

#define N_TOK 16384
#define VOCAB 50257
#define D_OUT 1024
#define TM 128
#define TN 128
#define TK 32

// ---------------- scratch (no allocations allowed) ----------------
__device__ int g_cnt[3];
__device__ int g_is64;
__device__ int g_tok[3 * N_TOK];
__device__ int g_loc[3 * N_TOK];
#define A_ELEMS (16384 * 1344)
#define AB1 ((size_t)16384 * 1024)
#define AB2 ((size_t)16384 * 1280)
__device__ __nv_bfloat16 g_Ahi[A_ELEMS];
__device__ __nv_bfloat16 g_Alo[A_ELEMS];
#define W_ELEMS (1024 * 1344)
#define WB1 ((size_t)1024 * 1024)
#define WB2 ((size_t)1024 * 1280)
__device__ __nv_bfloat16 g_Whi[W_ELEMS];
__device__ __nv_bfloat16 g_Wlo[W_ELEMS];

__constant__ int    c_h6[6]    = {1024, 256, 64, 1024, 256, 64};
__constant__ int    c_lc6[6]   = {7, 5, 3, 7, 5, 3};           // log2(h/8)
__constant__ size_t c_base6[6] = {0, AB1, AB2, 0, WB1, WB2};
__constant__ int    c_h[3]     = {1024, 256, 64};
__constant__ size_t c_baseA[3] = {0, AB1, AB2};
__constant__ size_t c_baseW[3] = {0, WB1, WB2};

// ---------------- helpers ----------------
__device__ __forceinline__ uint32_t smem_u32(const void* p) {
    uint32_t a;
    asm("{ .reg .u64 t; cvta.to.shared.u64 t, %1; cvt.u32.u64 %0, t; }" : "=r"(a) : "l"(p));
    return a;
}
__device__ __forceinline__ void ldsm4(uint32_t* r, uint32_t addr) {
    asm volatile("ldmatrix.sync.aligned.m8n8.x4.shared.b16 {%0,%1,%2,%3}, [%4];"
                 : "=r"(r[0]), "=r"(r[1]), "=r"(r[2]), "=r"(r[3]) : "r"(addr));
}
__device__ __forceinline__ void mma_bf16(float* c, const uint32_t* a, uint32_t b0, uint32_t b1) {
    asm volatile(
        "mma.sync.aligned.m16n8k16.row.col.f32.bf16.bf16.f32 "
        "{%0,%1,%2,%3}, {%4,%5,%6,%7}, {%8,%9}, {%0,%1,%2,%3};"
        : "+f"(c[0]), "+f"(c[1]), "+f"(c[2]), "+f"(c[3])
        : "r"(a[0]), "r"(a[1]), "r"(a[2]), "r"(a[3]), "r"(b0), "r"(b1));
}
__device__ __forceinline__ void cp16(uint32_t dst, const void* src) {
    asm volatile("cp.async.cg.shared.global [%0], [%1], 16;" :: "r"(dst), "l"(src));
}
#define CP_COMMIT() asm volatile("cp.async.commit_group;" ::: "memory")
#define CP_WAIT1()  asm volatile("cp.async.wait_group 1;" ::: "memory")

// smem tile row = 128B = 8 subs of 16B; subs 0-3 = hi(k0..31), 4-7 = lo.
__device__ __forceinline__ uint32_t sw_off(int row, int sub) {
    return (uint32_t)(row * 128 + ((sub ^ (row & 7)) << 4));
}

// ---------------- routing ----------------
__global__ void __launch_bounds__(1024) detect_kernel(const long long* __restrict__ p) {
    __shared__ int bad;
    if (threadIdx.x == 0) bad = 0;
    __syncthreads();
    long long v0 = p[threadIdx.x];
    long long v1 = p[threadIdx.x + 1024];
    long long v2 = p[threadIdx.x + 2048];
    long long v3 = p[threadIdx.x + 3072];
    long long v4 = p[threadIdx.x + 4096];
    long long v5 = p[threadIdx.x + 5120];
    long long v6 = p[threadIdx.x + 6144];
    long long v7 = p[threadIdx.x + 7168];
    bool ok = (v0 >= 0 && v0 < VOCAB) && (v1 >= 0 && v1 < VOCAB) &&
              (v2 >= 0 && v2 < VOCAB) && (v3 >= 0 && v3 < VOCAB) &&
              (v4 >= 0 && v4 < VOCAB) && (v5 >= 0 && v5 < VOCAB) &&
              (v6 >= 0 && v6 < VOCAB) && (v7 >= 0 && v7 < VOCAB);
    if (!ok) bad = 1;
    __syncthreads();
    if (threadIdx.x == 0) {
        g_is64 = (bad == 0);
        g_cnt[0] = 0; g_cnt[1] = 0; g_cnt[2] = 0;
    }
}

__global__ void classify_kernel(const void* __restrict__ idx_raw) {
    int n = blockIdx.x * blockDim.x + threadIdx.x;
    if (n >= N_TOK) return;
    int lane = threadIdx.x & 31;
    int v;
    if (g_is64) v = (int)((const long long*)idx_raw)[n];
    else        v = ((const int*)idx_raw)[n];
    v = min(max(v, 0), VOCAB - 1);
    int c  = (v >= 40000) ? 2 : ((v >= 20000) ? 1 : 0);
    int lo = (c == 2) ? 40000 : ((c == 1) ? 20000 : 0);
    int hicap = (c == 2) ? 10256 : 19999;
    int local = min(v - lo, hicap);
#pragma unroll
    for (int cc = 0; cc < 3; cc++) {
        unsigned m = __ballot_sync(0xFFFFFFFFu, c == cc);
        if (c == cc) {
            int leader = __ffs(m) - 1;
            int base = 0;
            if (lane == leader) base = atomicAdd(&g_cnt[cc], __popc(m));
            base = __shfl_sync(m, base, leader);
            int pos = base + __popc(m & ((1u << lane) - 1u));
            g_tok[cc * N_TOK + pos] = n;
            g_loc[cc * N_TOK + pos] = local;
        }
    }
}

// ---------------- fused pre-split converter (grid-stride) ----------------
__device__ __forceinline__ void split8(const float* src, uint4& hv, uint4& lv) {
    float4 v0 = *(const float4*)src;
    float4 v1 = *(const float4*)(src + 4);
    float f[8] = {v0.x, v0.y, v0.z, v0.w, v1.x, v1.y, v1.z, v1.w};
    __nv_bfloat16 hb[8], lb[8];
#pragma unroll
    for (int e = 0; e < 8; e++) {
        hb[e] = __float2bfloat16(f[e]);
        lb[e] = __float2bfloat16(f[e] - __bfloat162float(hb[e]));
    }
    __nv_bfloat162 h01 = __halves2bfloat162(hb[0], hb[1]);
    __nv_bfloat162 h23 = __halves2bfloat162(hb[2], hb[3]);
    __nv_bfloat162 h45 = __halves2bfloat162(hb[4], hb[5]);
    __nv_bfloat162 h67 = __halves2bfloat162(hb[6], hb[7]);
    __nv_bfloat162 l01 = __halves2bfloat162(lb[0], lb[1]);
    __nv_bfloat162 l23 = __halves2bfloat162(lb[2], lb[3]);
    __nv_bfloat162 l45 = __halves2bfloat162(lb[4], lb[5]);
    __nv_bfloat162 l67 = __halves2bfloat162(lb[6], lb[7]);
    hv = make_uint4(*(uint32_t*)&h01, *(uint32_t*)&h23, *(uint32_t*)&h45, *(uint32_t*)&h67);
    lv = make_uint4(*(uint32_t*)&l01, *(uint32_t*)&l23, *(uint32_t*)&l45, *(uint32_t*)&l67);
}

__global__ void conv_all(const float* __restrict__ e0, const float* __restrict__ e1,
                         const float* __restrict__ e2, const float* __restrict__ w0,
                         const float* __restrict__ w1, const float* __restrict__ w2)
{
    const int z  = blockIdx.z;
    const int h  = c_h6[z];
    const int lc = c_lc6[z];
    const size_t base = c_base6[z];
    const bool isA = (z < 3);
    const int cl = isA ? z : z - 3;
    const float* src_mat =
        (z == 0) ? e0 : (z == 1) ? e1 : (z == 2) ? e2 :
        (z == 3) ? w0 : (z == 4) ? w1 : w2;
    const int rows = isA ? g_cnt[cl] : D_OUT;
    const int total = rows << lc;
    const int stride = gridDim.x * blockDim.x;

    for (int id = blockIdx.x * blockDim.x + threadIdx.x; id < total; id += stride) {
        int s   = id >> lc;
        int off = (id & ((1 << lc) - 1)) << 3;
        int srow = isA ? g_loc[cl * N_TOK + s] : s;
        uint4 hv, lv;
        split8(src_mat + (size_t)srow * h + off, hv, lv);
        size_t d = base + (size_t)s * h + off;
        if (isA) { *(uint4*)&g_Ahi[d] = hv; *(uint4*)&g_Alo[d] = lv; }
        else     { *(uint4*)&g_Whi[d] = hv; *(uint4*)&g_Wlo[d] = lv; }
    }
}

// ---------------- GEMM: 3-stage pipeline, 2 CTAs/SM ----------------
#define SM_TOK 0
#define SM_A(i) (1024 + (i) * 16384)
#define SM_B(i) (50176 + (i) * 16384)
#define SM_TOTAL 99328

__device__ __forceinline__ void stage_tiles(
    uint32_t sb, int buf, int t,
    size_t baseA, size_t baseW, int m0, int n0, int k0, int h)
{
#pragma unroll
    for (int i = 0; i < 4; i++) {
        int cid = t + i * 256;
        int row = cid >> 3, sub = cid & 7;
        const __nv_bfloat16* src = (sub < 4 ? g_Ahi : g_Alo) +
            baseA + (size_t)(m0 + row) * h + k0 + (sub & 3) * 8;
        cp16(sb + SM_A(buf) + sw_off(row, sub), src);
    }
#pragma unroll
    for (int i = 0; i < 4; i++) {
        int cid = t + i * 256;
        int row = cid >> 3, sub = cid & 7;
        const __nv_bfloat16* src = (sub < 4 ? g_Whi : g_Wlo) +
            baseW + (size_t)(n0 + row) * h + k0 + (sub & 3) * 8;
        cp16(sb + SM_B(buf) + sw_off(row, sub), src);
    }
}

__global__ void __launch_bounds__(256, 2) gemm_mma(float* __restrict__ out)
{
    const int cl  = blockIdx.z;
    const int cnt = g_cnt[cl];
    const int m0  = blockIdx.x * TM;
    if (m0 >= cnt) return;
    const int h     = c_h[cl];
    const size_t baseA = c_baseA[cl];
    const size_t baseW = c_baseW[cl];
    const int n0  = blockIdx.y * TN;

    extern __shared__ __align__(16) char smem[];
    const uint32_t sb = smem_u32(smem);
    int* s_tok = (int*)(smem + SM_TOK);

    const int t    = threadIdx.x;
    const int lane = t & 31;
    const int wid  = t >> 5;
    const int wm   = wid & 1;       // 2 M groups of 64 rows
    const int wn   = wid >> 1;      // 4 N groups of 32 cols
    const int li   = lane & 7;
    const int sel  = lane >> 3;

    if (t < TM) {
        int m = m0 + t;
        s_tok[t] = (m < cnt) ? g_tok[cl * N_TOK + m] : -1;
    }

    const int nkt = h / TK;
    stage_tiles(sb, 0, t, baseA, baseW, m0, n0, 0, h);
    CP_COMMIT();
    if (nkt > 1) stage_tiles(sb, 1, t, baseA, baseW, m0, n0, TK, h);
    CP_COMMIT();

    float acc[4][4][4];
#pragma unroll
    for (int i = 0; i < 4; i++)
#pragma unroll
        for (int j = 0; j < 4; j++)
#pragma unroll
            for (int q = 0; q < 4; q++) acc[i][j][q] = 0.0f;

    int buf = 0;
    for (int kt = 0; kt < nkt; kt++) {
        CP_WAIT1();          // group kt complete
        __syncthreads();     // all threads finished computing kt-1
        if (kt + 2 < nkt) {
            int nb = buf + 2; if (nb >= 3) nb -= 3;
            stage_tiles(sb, nb, t, baseA, baseW, m0, n0, (kt + 2) * TK, h);
        }
        CP_COMMIT();

        const uint32_t bA = sb + SM_A(buf);
        const uint32_t bB = sb + SM_B(buf);
#pragma unroll
        for (int kh = 0; kh < 2; kh++) {
            const int sh = 2 * kh;
            const int sl = 4 + 2 * kh;
            uint32_t ah[4][4], al[4][4];
#pragma unroll
            for (int mf = 0; mf < 4; mf++) {
                int row = wm * 64 + mf * 16 + li + ((sel & 1) ? 8 : 0);
                ldsm4(ah[mf], bA + sw_off(row, sh + ((sel >> 1) & 1)));
                ldsm4(al[mf], bA + sw_off(row, sl + ((sel >> 1) & 1)));
            }
#pragma unroll
            for (int pp = 0; pp < 2; pp++) {
                int brow = wn * 32 + pp * 16 + li + ((sel >> 1) ? 8 : 0);
                uint32_t bh[4], bl[4];
                ldsm4(bh, bB + sw_off(brow, sh + (sel & 1)));
                ldsm4(bl, bB + sw_off(brow, sl + (sel & 1)));
                // 3 passes (hh, hl, lh): per-accumulator order unchanged
                // (hh -> hl -> lh), but RAW-dependent MMAs are now separated
                // by 8 independent ones.
#pragma unroll
                for (int mf = 0; mf < 4; mf++) {
                    mma_bf16(acc[mf][2 * pp],     ah[mf], bh[0], bh[1]);
                    mma_bf16(acc[mf][2 * pp + 1], ah[mf], bh[2], bh[3]);
                }
#pragma unroll
                for (int mf = 0; mf < 4; mf++) {
                    mma_bf16(acc[mf][2 * pp],     ah[mf], bl[0], bl[1]);
                    mma_bf16(acc[mf][2 * pp + 1], ah[mf], bl[2], bl[3]);
                }
#pragma unroll
                for (int mf = 0; mf < 4; mf++) {
                    mma_bf16(acc[mf][2 * pp],     al[mf], bh[0], bh[1]);
                    mma_bf16(acc[mf][2 * pp + 1], al[mf], bh[2], bh[3]);
                }
            }
        }
        if (++buf == 3) buf = 0;
    }

    const int g  = lane >> 2;
    const int tq = lane & 3;
#pragma unroll
    for (int mf = 0; mf < 4; mf++) {
        int r0 = wm * 64 + mf * 16 + g;
        int tokA = s_tok[r0];
        int tokB = s_tok[r0 + 8];
#pragma unroll
        for (int nf = 0; nf < 4; nf++) {
            int col = n0 + wn * 32 + nf * 8 + tq * 2;
            if (tokA >= 0)
                *(float2*)&out[(size_t)tokA * D_OUT + col] =
                    make_float2(acc[mf][nf][0], acc[mf][nf][1]);
            if (tokB >= 0)
                *(float2*)&out[(size_t)tokB * D_OUT + col] =
                    make_float2(acc[mf][nf][2], acc[mf][nf][3]);
        }
    }
}

extern "C" void kernel_launch(void* const* d_in, const int* in_sizes, int n_in,
                              void* d_out, int out_size)
{
    const void*  idx  = d_in[0];
    const float* emb0 = (const float*)d_in[1];
    const float* w0   = (const float*)d_in[2];
    const float* emb1 = (const float*)d_in[3];
    const float* w1   = (const float*)d_in[4];
    const float* emb2 = (const float*)d_in[5];
    const float* w2   = (const float*)d_in[6];
    float* out = (float*)d_out;

    cudaFuncSetAttribute(gemm_mma, cudaFuncAttributeMaxDynamicSharedMemorySize, SM_TOTAL);

    detect_kernel<<<1, 1024>>>((const long long*)idx);
    classify_kernel<<<N_TOK / 256, 256>>>(idx);

    { dim3 g(768, 1, 6); conv_all<<<g, 256>>>(emb0, emb1, emb2, w0, w1, w2); }

    { dim3 g(N_TOK / TM, D_OUT / TN, 3); gemm_mma<<<g, 256, SM_TOTAL>>>(out); }
}

// round 13
// speedup vs baseline: 1.0113x; 1.0113x over previous
#include <cuda_runtime.h>
#include <cuda_bf16.h>
#include <cstdint>

// AdaptiveEmbedding: 3-cluster gather+projection.
// detect -> classify (warp-aggregated) -> conv_all (grid-stride bf16 hi/lo
// pre-split) -> z-grid cp.async 3-stage pipelined mma.sync GEMM (2 CTAs/SM).
// R13: R11 loop with the two acc chains interleaved (RAW dist 2, ah reuse kept).
// Baseline-PTX only (harness targets sm_103, no 'a': no tcgen05).

#define N_TOK 16384
#define VOCAB 50257
#define D_OUT 1024
#define TM 128
#define TN 128
#define TK 32

// ---------------- scratch (no allocations allowed) ----------------
__device__ int g_cnt[3];
__device__ int g_is64;
__device__ int g_tok[3 * N_TOK];
__device__ int g_loc[3 * N_TOK];
#define A_ELEMS (16384 * 1344)
#define AB1 ((size_t)16384 * 1024)
#define AB2 ((size_t)16384 * 1280)
__device__ __nv_bfloat16 g_Ahi[A_ELEMS];
__device__ __nv_bfloat16 g_Alo[A_ELEMS];
#define W_ELEMS (1024 * 1344)
#define WB1 ((size_t)1024 * 1024)
#define WB2 ((size_t)1024 * 1280)
__device__ __nv_bfloat16 g_Whi[W_ELEMS];
__device__ __nv_bfloat16 g_Wlo[W_ELEMS];

__constant__ int    c_h6[6]    = {1024, 256, 64, 1024, 256, 64};
__constant__ int    c_lc6[6]   = {7, 5, 3, 7, 5, 3};           // log2(h/8)
__constant__ size_t c_base6[6] = {0, AB1, AB2, 0, WB1, WB2};
__constant__ int    c_h[3]     = {1024, 256, 64};
__constant__ size_t c_baseA[3] = {0, AB1, AB2};
__constant__ size_t c_baseW[3] = {0, WB1, WB2};

// ---------------- helpers ----------------
__device__ __forceinline__ uint32_t smem_u32(const void* p) {
    uint32_t a;
    asm("{ .reg .u64 t; cvta.to.shared.u64 t, %1; cvt.u32.u64 %0, t; }" : "=r"(a) : "l"(p));
    return a;
}
__device__ __forceinline__ void ldsm4(uint32_t* r, uint32_t addr) {
    asm volatile("ldmatrix.sync.aligned.m8n8.x4.shared.b16 {%0,%1,%2,%3}, [%4];"
                 : "=r"(r[0]), "=r"(r[1]), "=r"(r[2]), "=r"(r[3]) : "r"(addr));
}
__device__ __forceinline__ void mma_bf16(float* c, const uint32_t* a, uint32_t b0, uint32_t b1) {
    asm volatile(
        "mma.sync.aligned.m16n8k16.row.col.f32.bf16.bf16.f32 "
        "{%0,%1,%2,%3}, {%4,%5,%6,%7}, {%8,%9}, {%0,%1,%2,%3};"
        : "+f"(c[0]), "+f"(c[1]), "+f"(c[2]), "+f"(c[3])
        : "r"(a[0]), "r"(a[1]), "r"(a[2]), "r"(a[3]), "r"(b0), "r"(b1));
}
__device__ __forceinline__ void cp16(uint32_t dst, const void* src) {
    asm volatile("cp.async.cg.shared.global [%0], [%1], 16;" :: "r"(dst), "l"(src));
}
#define CP_COMMIT() asm volatile("cp.async.commit_group;" ::: "memory")
#define CP_WAIT1()  asm volatile("cp.async.wait_group 1;" ::: "memory")

// smem tile row = 128B = 8 subs of 16B; subs 0-3 = hi(k0..31), 4-7 = lo.
__device__ __forceinline__ uint32_t sw_off(int row, int sub) {
    return (uint32_t)(row * 128 + ((sub ^ (row & 7)) << 4));
}

// ---------------- routing ----------------
__global__ void __launch_bounds__(1024) detect_kernel(const long long* __restrict__ p) {
    __shared__ int bad;
    if (threadIdx.x == 0) bad = 0;
    __syncthreads();
    long long v0 = p[threadIdx.x];
    long long v1 = p[threadIdx.x + 1024];
    long long v2 = p[threadIdx.x + 2048];
    long long v3 = p[threadIdx.x + 3072];
    long long v4 = p[threadIdx.x + 4096];
    long long v5 = p[threadIdx.x + 5120];
    long long v6 = p[threadIdx.x + 6144];
    long long v7 = p[threadIdx.x + 7168];
    bool ok = (v0 >= 0 && v0 < VOCAB) && (v1 >= 0 && v1 < VOCAB) &&
              (v2 >= 0 && v2 < VOCAB) && (v3 >= 0 && v3 < VOCAB) &&
              (v4 >= 0 && v4 < VOCAB) && (v5 >= 0 && v5 < VOCAB) &&
              (v6 >= 0 && v6 < VOCAB) && (v7 >= 0 && v7 < VOCAB);
    if (!ok) bad = 1;
    __syncthreads();
    if (threadIdx.x == 0) {
        g_is64 = (bad == 0);
        g_cnt[0] = 0; g_cnt[1] = 0; g_cnt[2] = 0;
    }
}

__global__ void classify_kernel(const void* __restrict__ idx_raw) {
    int n = blockIdx.x * blockDim.x + threadIdx.x;
    if (n >= N_TOK) return;
    int lane = threadIdx.x & 31;
    int v;
    if (g_is64) v = (int)((const long long*)idx_raw)[n];
    else        v = ((const int*)idx_raw)[n];
    v = min(max(v, 0), VOCAB - 1);
    int c  = (v >= 40000) ? 2 : ((v >= 20000) ? 1 : 0);
    int lo = (c == 2) ? 40000 : ((c == 1) ? 20000 : 0);
    int hicap = (c == 2) ? 10256 : 19999;
    int local = min(v - lo, hicap);
#pragma unroll
    for (int cc = 0; cc < 3; cc++) {
        unsigned m = __ballot_sync(0xFFFFFFFFu, c == cc);
        if (c == cc) {
            int leader = __ffs(m) - 1;
            int base = 0;
            if (lane == leader) base = atomicAdd(&g_cnt[cc], __popc(m));
            base = __shfl_sync(m, base, leader);
            int pos = base + __popc(m & ((1u << lane) - 1u));
            g_tok[cc * N_TOK + pos] = n;
            g_loc[cc * N_TOK + pos] = local;
        }
    }
}

// ---------------- fused pre-split converter (grid-stride) ----------------
__device__ __forceinline__ void split8(const float* src, uint4& hv, uint4& lv) {
    float4 v0 = *(const float4*)src;
    float4 v1 = *(const float4*)(src + 4);
    float f[8] = {v0.x, v0.y, v0.z, v0.w, v1.x, v1.y, v1.z, v1.w};
    __nv_bfloat16 hb[8], lb[8];
#pragma unroll
    for (int e = 0; e < 8; e++) {
        hb[e] = __float2bfloat16(f[e]);
        lb[e] = __float2bfloat16(f[e] - __bfloat162float(hb[e]));
    }
    __nv_bfloat162 h01 = __halves2bfloat162(hb[0], hb[1]);
    __nv_bfloat162 h23 = __halves2bfloat162(hb[2], hb[3]);
    __nv_bfloat162 h45 = __halves2bfloat162(hb[4], hb[5]);
    __nv_bfloat162 h67 = __halves2bfloat162(hb[6], hb[7]);
    __nv_bfloat162 l01 = __halves2bfloat162(lb[0], lb[1]);
    __nv_bfloat162 l23 = __halves2bfloat162(lb[2], lb[3]);
    __nv_bfloat162 l45 = __halves2bfloat162(lb[4], lb[5]);
    __nv_bfloat162 l67 = __halves2bfloat162(lb[6], lb[7]);
    hv = make_uint4(*(uint32_t*)&h01, *(uint32_t*)&h23, *(uint32_t*)&h45, *(uint32_t*)&h67);
    lv = make_uint4(*(uint32_t*)&l01, *(uint32_t*)&l23, *(uint32_t*)&l45, *(uint32_t*)&l67);
}

__global__ void conv_all(const float* __restrict__ e0, const float* __restrict__ e1,
                         const float* __restrict__ e2, const float* __restrict__ w0,
                         const float* __restrict__ w1, const float* __restrict__ w2)
{
    const int z  = blockIdx.z;
    const int h  = c_h6[z];
    const int lc = c_lc6[z];
    const size_t base = c_base6[z];
    const bool isA = (z < 3);
    const int cl = isA ? z : z - 3;
    const float* src_mat =
        (z == 0) ? e0 : (z == 1) ? e1 : (z == 2) ? e2 :
        (z == 3) ? w0 : (z == 4) ? w1 : w2;
    const int rows = isA ? g_cnt[cl] : D_OUT;
    const int total = rows << lc;
    const int stride = gridDim.x * blockDim.x;

    for (int id = blockIdx.x * blockDim.x + threadIdx.x; id < total; id += stride) {
        int s   = id >> lc;
        int off = (id & ((1 << lc) - 1)) << 3;
        int srow = isA ? g_loc[cl * N_TOK + s] : s;
        uint4 hv, lv;
        split8(src_mat + (size_t)srow * h + off, hv, lv);
        size_t d = base + (size_t)s * h + off;
        if (isA) { *(uint4*)&g_Ahi[d] = hv; *(uint4*)&g_Alo[d] = lv; }
        else     { *(uint4*)&g_Whi[d] = hv; *(uint4*)&g_Wlo[d] = lv; }
    }
}

// ---------------- GEMM: 3-stage pipeline, 2 CTAs/SM ----------------
#define SM_TOK 0
#define SM_A(i) (1024 + (i) * 16384)
#define SM_B(i) (50176 + (i) * 16384)
#define SM_TOTAL 99328

__device__ __forceinline__ void stage_tiles(
    uint32_t sb, int buf, int t,
    size_t baseA, size_t baseW, int m0, int n0, int k0, int h)
{
#pragma unroll
    for (int i = 0; i < 4; i++) {
        int cid = t + i * 256;
        int row = cid >> 3, sub = cid & 7;
        const __nv_bfloat16* src = (sub < 4 ? g_Ahi : g_Alo) +
            baseA + (size_t)(m0 + row) * h + k0 + (sub & 3) * 8;
        cp16(sb + SM_A(buf) + sw_off(row, sub), src);
    }
#pragma unroll
    for (int i = 0; i < 4; i++) {
        int cid = t + i * 256;
        int row = cid >> 3, sub = cid & 7;
        const __nv_bfloat16* src = (sub < 4 ? g_Whi : g_Wlo) +
            baseW + (size_t)(n0 + row) * h + k0 + (sub & 3) * 8;
        cp16(sb + SM_B(buf) + sw_off(row, sub), src);
    }
}

__global__ void __launch_bounds__(256, 2) gemm_mma(float* __restrict__ out)
{
    const int cl  = blockIdx.z;
    const int cnt = g_cnt[cl];
    const int m0  = blockIdx.x * TM;
    if (m0 >= cnt) return;
    const int h     = c_h[cl];
    const size_t baseA = c_baseA[cl];
    const size_t baseW = c_baseW[cl];
    const int n0  = blockIdx.y * TN;

    extern __shared__ __align__(16) char smem[];
    const uint32_t sb = smem_u32(smem);
    int* s_tok = (int*)(smem + SM_TOK);

    const int t    = threadIdx.x;
    const int lane = t & 31;
    const int wid  = t >> 5;
    const int wm   = wid & 1;       // 2 M groups of 64 rows
    const int wn   = wid >> 1;      // 4 N groups of 32 cols
    const int li   = lane & 7;
    const int sel  = lane >> 3;

    if (t < TM) {
        int m = m0 + t;
        s_tok[t] = (m < cnt) ? g_tok[cl * N_TOK + m] : -1;
    }

    const int nkt = h / TK;
    stage_tiles(sb, 0, t, baseA, baseW, m0, n0, 0, h);
    CP_COMMIT();
    if (nkt > 1) stage_tiles(sb, 1, t, baseA, baseW, m0, n0, TK, h);
    CP_COMMIT();

    float acc[4][4][4];
#pragma unroll
    for (int i = 0; i < 4; i++)
#pragma unroll
        for (int j = 0; j < 4; j++)
#pragma unroll
            for (int q = 0; q < 4; q++) acc[i][j][q] = 0.0f;

    int buf = 0;
    for (int kt = 0; kt < nkt; kt++) {
        CP_WAIT1();          // group kt complete
        __syncthreads();     // all threads finished computing kt-1
        if (kt + 2 < nkt) {
            int nb = buf + 2; if (nb >= 3) nb -= 3;
            stage_tiles(sb, nb, t, baseA, baseW, m0, n0, (kt + 2) * TK, h);
        }
        CP_COMMIT();

        const uint32_t bA = sb + SM_A(buf);
        const uint32_t bB = sb + SM_B(buf);
#pragma unroll
        for (int kh = 0; kh < 2; kh++) {
            const int sh = 2 * kh;
            const int sl = 4 + 2 * kh;
            uint32_t ah[4][4], al[4][4];
#pragma unroll
            for (int mf = 0; mf < 4; mf++) {
                int row = wm * 64 + mf * 16 + li + ((sel & 1) ? 8 : 0);
                ldsm4(ah[mf], bA + sw_off(row, sh + ((sel >> 1) & 1)));
                ldsm4(al[mf], bA + sw_off(row, sl + ((sel >> 1) & 1)));
            }
#pragma unroll
            for (int pp = 0; pp < 2; pp++) {
                int brow = wn * 32 + pp * 16 + li + ((sel >> 1) ? 8 : 0);
                uint32_t bh[4], bl[4];
                ldsm4(bh, bB + sw_off(brow, sh + (sel & 1)));
                ldsm4(bl, bB + sw_off(brow, sl + (sel & 1)));
                // Interleave the two independent acc chains: per-acc order is
                // still hh -> hl -> lh (bit-identical), ah reused across the
                // first four MMAs, same-acc RAW distance = 2.
#pragma unroll
                for (int mf = 0; mf < 4; mf++) {
                    mma_bf16(acc[mf][2 * pp],     ah[mf], bh[0], bh[1]);
                    mma_bf16(acc[mf][2 * pp + 1], ah[mf], bh[2], bh[3]);
                    mma_bf16(acc[mf][2 * pp],     ah[mf], bl[0], bl[1]);
                    mma_bf16(acc[mf][2 * pp + 1], ah[mf], bl[2], bl[3]);
                    mma_bf16(acc[mf][2 * pp],     al[mf], bh[0], bh[1]);
                    mma_bf16(acc[mf][2 * pp + 1], al[mf], bh[2], bh[3]);
                }
            }
        }
        if (++buf == 3) buf = 0;
    }

    const int g  = lane >> 2;
    const int tq = lane & 3;
#pragma unroll
    for (int mf = 0; mf < 4; mf++) {
        int r0 = wm * 64 + mf * 16 + g;
        int tokA = s_tok[r0];
        int tokB = s_tok[r0 + 8];
#pragma unroll
        for (int nf = 0; nf < 4; nf++) {
            int col = n0 + wn * 32 + nf * 8 + tq * 2;
            if (tokA >= 0)
                *(float2*)&out[(size_t)tokA * D_OUT + col] =
                    make_float2(acc[mf][nf][0], acc[mf][nf][1]);
            if (tokB >= 0)
                *(float2*)&out[(size_t)tokB * D_OUT + col] =
                    make_float2(acc[mf][nf][2], acc[mf][nf][3]);
        }
    }
}

extern "C" void kernel_launch(void* const* d_in, const int* in_sizes, int n_in,
                              void* d_out, int out_size)
{
    const void*  idx  = d_in[0];
    const float* emb0 = (const float*)d_in[1];
    const float* w0   = (const float*)d_in[2];
    const float* emb1 = (const float*)d_in[3];
    const float* w1   = (const float*)d_in[4];
    const float* emb2 = (const float*)d_in[5];
    const float* w2   = (const float*)d_in[6];
    float* out = (float*)d_out;

    cudaFuncSetAttribute(gemm_mma, cudaFuncAttributeMaxDynamicSharedMemorySize, SM_TOTAL);

    detect_kernel<<<1, 1024>>>((const long long*)idx);
    classify_kernel<<<N_TOK / 256, 256>>>(idx);

    { dim3 g(768, 1, 6); conv_all<<<g, 256>>>(emb0, emb1, emb2, w0, w1, w2); }

    { dim3 g(N_TOK / TM, D_OUT / TN, 3); gemm_mma<<<g, 256, SM_TOTAL>>>(out); }
}

// round 14
// speedup vs baseline: 1.0282x; 1.0167x over previous
#include <cuda_runtime.h>
#include <cuda_bf16.h>
#include <cstdint>

// AdaptiveEmbedding: 3-cluster gather+projection.
// detect -> classify (warp-aggregated) -> conv_flat (balanced grid-stride
// bf16 hi/lo pre-split over all 6 matrices) -> z-grid cp.async 3-stage
// pipelined mma.sync GEMM (2 CTAs/SM).  GEMM inner loop = R11 verbatim (frozen:
// both reorder experiments regressed 135->212us at equal tensor%).
// Baseline-PTX only (harness targets sm_103, no 'a': no tcgen05).

#define N_TOK 16384
#define VOCAB 50257
#define D_OUT 1024
#define TM 128
#define TN 128
#define TK 32

// ---------------- scratch (no allocations allowed) ----------------
__device__ int g_cnt[3];
__device__ int g_is64;
__device__ int g_tok[3 * N_TOK];
__device__ int g_loc[3 * N_TOK];
#define A_ELEMS (16384 * 1344)
#define AB1 ((size_t)16384 * 1024)
#define AB2 ((size_t)16384 * 1280)
__device__ __nv_bfloat16 g_Ahi[A_ELEMS];
__device__ __nv_bfloat16 g_Alo[A_ELEMS];
#define W_ELEMS (1024 * 1344)
#define WB1 ((size_t)1024 * 1024)
#define WB2 ((size_t)1024 * 1280)
__device__ __nv_bfloat16 g_Whi[W_ELEMS];
__device__ __nv_bfloat16 g_Wlo[W_ELEMS];

__constant__ int    c_h[3]     = {1024, 256, 64};
__constant__ size_t c_baseA[3] = {0, AB1, AB2};
__constant__ size_t c_baseW[3] = {0, WB1, WB2};

// ---------------- helpers ----------------
__device__ __forceinline__ uint32_t smem_u32(const void* p) {
    uint32_t a;
    asm("{ .reg .u64 t; cvta.to.shared.u64 t, %1; cvt.u32.u64 %0, t; }" : "=r"(a) : "l"(p));
    return a;
}
__device__ __forceinline__ void ldsm4(uint32_t* r, uint32_t addr) {
    asm volatile("ldmatrix.sync.aligned.m8n8.x4.shared.b16 {%0,%1,%2,%3}, [%4];"
                 : "=r"(r[0]), "=r"(r[1]), "=r"(r[2]), "=r"(r[3]) : "r"(addr));
}
__device__ __forceinline__ void mma_bf16(float* c, const uint32_t* a, uint32_t b0, uint32_t b1) {
    asm volatile(
        "mma.sync.aligned.m16n8k16.row.col.f32.bf16.bf16.f32 "
        "{%0,%1,%2,%3}, {%4,%5,%6,%7}, {%8,%9}, {%0,%1,%2,%3};"
        : "+f"(c[0]), "+f"(c[1]), "+f"(c[2]), "+f"(c[3])
        : "r"(a[0]), "r"(a[1]), "r"(a[2]), "r"(a[3]), "r"(b0), "r"(b1));
}
__device__ __forceinline__ void cp16(uint32_t dst, const void* src) {
    asm volatile("cp.async.cg.shared.global [%0], [%1], 16;" :: "r"(dst), "l"(src));
}
#define CP_COMMIT() asm volatile("cp.async.commit_group;" ::: "memory")
#define CP_WAIT1()  asm volatile("cp.async.wait_group 1;" ::: "memory")

// smem tile row = 128B = 8 subs of 16B; subs 0-3 = hi(k0..31), 4-7 = lo.
__device__ __forceinline__ uint32_t sw_off(int row, int sub) {
    return (uint32_t)(row * 128 + ((sub ^ (row & 7)) << 4));
}

// ---------------- routing ----------------
__global__ void __launch_bounds__(1024) detect_kernel(const long long* __restrict__ p) {
    __shared__ int bad;
    if (threadIdx.x == 0) bad = 0;
    __syncthreads();
    long long v0 = p[threadIdx.x];
    long long v1 = p[threadIdx.x + 1024];
    long long v2 = p[threadIdx.x + 2048];
    long long v3 = p[threadIdx.x + 3072];
    long long v4 = p[threadIdx.x + 4096];
    long long v5 = p[threadIdx.x + 5120];
    long long v6 = p[threadIdx.x + 6144];
    long long v7 = p[threadIdx.x + 7168];
    bool ok = (v0 >= 0 && v0 < VOCAB) && (v1 >= 0 && v1 < VOCAB) &&
              (v2 >= 0 && v2 < VOCAB) && (v3 >= 0 && v3 < VOCAB) &&
              (v4 >= 0 && v4 < VOCAB) && (v5 >= 0 && v5 < VOCAB) &&
              (v6 >= 0 && v6 < VOCAB) && (v7 >= 0 && v7 < VOCAB);
    if (!ok) bad = 1;
    __syncthreads();
    if (threadIdx.x == 0) {
        g_is64 = (bad == 0);
        g_cnt[0] = 0; g_cnt[1] = 0; g_cnt[2] = 0;
    }
}

__global__ void classify_kernel(const void* __restrict__ idx_raw) {
    int n = blockIdx.x * blockDim.x + threadIdx.x;
    if (n >= N_TOK) return;
    int lane = threadIdx.x & 31;
    int v;
    if (g_is64) v = (int)((const long long*)idx_raw)[n];
    else        v = ((const int*)idx_raw)[n];
    v = min(max(v, 0), VOCAB - 1);
    int c  = (v >= 40000) ? 2 : ((v >= 20000) ? 1 : 0);
    int lo = (c == 2) ? 40000 : ((c == 1) ? 20000 : 0);
    int hicap = (c == 2) ? 10256 : 19999;
    int local = min(v - lo, hicap);
#pragma unroll
    for (int cc = 0; cc < 3; cc++) {
        unsigned m = __ballot_sync(0xFFFFFFFFu, c == cc);
        if (c == cc) {
            int leader = __ffs(m) - 1;
            int base = 0;
            if (lane == leader) base = atomicAdd(&g_cnt[cc], __popc(m));
            base = __shfl_sync(m, base, leader);
            int pos = base + __popc(m & ((1u << lane) - 1u));
            g_tok[cc * N_TOK + pos] = n;
            g_loc[cc * N_TOK + pos] = local;
        }
    }
}

// ---------------- balanced flat pre-split converter ----------------
__device__ __forceinline__ void split8(const float* src, uint4& hv, uint4& lv) {
    float4 v0 = *(const float4*)src;
    float4 v1 = *(const float4*)(src + 4);
    float f[8] = {v0.x, v0.y, v0.z, v0.w, v1.x, v1.y, v1.z, v1.w};
    __nv_bfloat16 hb[8], lb[8];
#pragma unroll
    for (int e = 0; e < 8; e++) {
        hb[e] = __float2bfloat16(f[e]);
        lb[e] = __float2bfloat16(f[e] - __bfloat162float(hb[e]));
    }
    __nv_bfloat162 h01 = __halves2bfloat162(hb[0], hb[1]);
    __nv_bfloat162 h23 = __halves2bfloat162(hb[2], hb[3]);
    __nv_bfloat162 h45 = __halves2bfloat162(hb[4], hb[5]);
    __nv_bfloat162 h67 = __halves2bfloat162(hb[6], hb[7]);
    __nv_bfloat162 l01 = __halves2bfloat162(lb[0], lb[1]);
    __nv_bfloat162 l23 = __halves2bfloat162(lb[2], lb[3]);
    __nv_bfloat162 l45 = __halves2bfloat162(lb[4], lb[5]);
    __nv_bfloat162 l67 = __halves2bfloat162(lb[6], lb[7]);
    hv = make_uint4(*(uint32_t*)&h01, *(uint32_t*)&h23, *(uint32_t*)&h45, *(uint32_t*)&h67);
    lv = make_uint4(*(uint32_t*)&l01, *(uint32_t*)&l23, *(uint32_t*)&l45, *(uint32_t*)&l67);
}

// Segments (8-float chunks): 0..2 = gathered A rows per cluster, 3..5 = weights.
// One balanced grid-stride loop over the concatenated chunk space.
__global__ void conv_flat(const float* __restrict__ e0, const float* __restrict__ e1,
                          const float* __restrict__ e2, const float* __restrict__ w0,
                          const float* __restrict__ w1, const float* __restrict__ w2)
{
    const int t0 = g_cnt[0] << 7;            // cluster0 A: h=1024 -> 128 chunks/row
    const int t1 = g_cnt[1] << 5;
    const int t2 = g_cnt[2] << 3;
    const int u0 = D_OUT << 7, u1 = D_OUT << 5, u2 = D_OUT << 3;
    const int e0c = t0, e1c = e0c + t1, e2c = e1c + t2;
    const int e3c = e2c + u0, e4c = e3c + u1, e5c = e4c + u2;
    const int stride = gridDim.x * blockDim.x;

    for (int id = blockIdx.x * blockDim.x + threadIdx.x; id < e5c; id += stride) {
        int z, lid;
        if      (id < e0c) { z = 0; lid = id; }
        else if (id < e1c) { z = 1; lid = id - e0c; }
        else if (id < e2c) { z = 2; lid = id - e1c; }
        else if (id < e3c) { z = 3; lid = id - e2c; }
        else if (id < e4c) { z = 4; lid = id - e3c; }
        else               { z = 5; lid = id - e4c; }
        const bool isA = (z < 3);
        const int cl  = isA ? z : z - 3;
        const int h   = c_h[cl];
        const int lc  = (cl == 0) ? 7 : (cl == 1) ? 5 : 3;
        int s   = lid >> lc;
        int off = (lid & ((1 << lc) - 1)) << 3;
        int srow = isA ? g_loc[cl * N_TOK + s] : s;
        const float* src_mat =
            (z == 0) ? e0 : (z == 1) ? e1 : (z == 2) ? e2 :
            (z == 3) ? w0 : (z == 4) ? w1 : w2;
        uint4 hv, lv;
        split8(src_mat + (size_t)srow * h + off, hv, lv);
        size_t d = (isA ? c_baseA[cl] : c_baseW[cl]) + (size_t)s * h + off;
        if (isA) { *(uint4*)&g_Ahi[d] = hv; *(uint4*)&g_Alo[d] = lv; }
        else     { *(uint4*)&g_Whi[d] = hv; *(uint4*)&g_Wlo[d] = lv; }
    }
}

// ---------------- GEMM: 3-stage pipeline, 2 CTAs/SM (R11 verbatim) ----------------
#define SM_TOK 0
#define SM_A(i) (1024 + (i) * 16384)
#define SM_B(i) (50176 + (i) * 16384)
#define SM_TOTAL 99328

__device__ __forceinline__ void stage_tiles(
    uint32_t sb, int buf, int t,
    size_t baseA, size_t baseW, int m0, int n0, int k0, int h)
{
#pragma unroll
    for (int i = 0; i < 4; i++) {
        int cid = t + i * 256;
        int row = cid >> 3, sub = cid & 7;
        const __nv_bfloat16* src = (sub < 4 ? g_Ahi : g_Alo) +
            baseA + (size_t)(m0 + row) * h + k0 + (sub & 3) * 8;
        cp16(sb + SM_A(buf) + sw_off(row, sub), src);
    }
#pragma unroll
    for (int i = 0; i < 4; i++) {
        int cid = t + i * 256;
        int row = cid >> 3, sub = cid & 7;
        const __nv_bfloat16* src = (sub < 4 ? g_Whi : g_Wlo) +
            baseW + (size_t)(n0 + row) * h + k0 + (sub & 3) * 8;
        cp16(sb + SM_B(buf) + sw_off(row, sub), src);
    }
}

__global__ void __launch_bounds__(256, 2) gemm_mma(float* __restrict__ out)
{
    const int cl  = blockIdx.z;
    const int cnt = g_cnt[cl];
    const int m0  = blockIdx.x * TM;
    if (m0 >= cnt) return;
    const int h     = c_h[cl];
    const size_t baseA = c_baseA[cl];
    const size_t baseW = c_baseW[cl];
    const int n0  = blockIdx.y * TN;

    extern __shared__ __align__(16) char smem[];
    const uint32_t sb = smem_u32(smem);
    int* s_tok = (int*)(smem + SM_TOK);

    const int t    = threadIdx.x;
    const int lane = t & 31;
    const int wid  = t >> 5;
    const int wm   = wid & 1;       // 2 M groups of 64 rows
    const int wn   = wid >> 1;      // 4 N groups of 32 cols
    const int li   = lane & 7;
    const int sel  = lane >> 3;

    if (t < TM) {
        int m = m0 + t;
        s_tok[t] = (m < cnt) ? g_tok[cl * N_TOK + m] : -1;
    }

    const int nkt = h / TK;
    stage_tiles(sb, 0, t, baseA, baseW, m0, n0, 0, h);
    CP_COMMIT();
    if (nkt > 1) stage_tiles(sb, 1, t, baseA, baseW, m0, n0, TK, h);
    CP_COMMIT();

    float acc[4][4][4];
#pragma unroll
    for (int i = 0; i < 4; i++)
#pragma unroll
        for (int j = 0; j < 4; j++)
#pragma unroll
            for (int q = 0; q < 4; q++) acc[i][j][q] = 0.0f;

    int buf = 0;
    for (int kt = 0; kt < nkt; kt++) {
        CP_WAIT1();          // group kt complete
        __syncthreads();     // all threads finished computing kt-1
        if (kt + 2 < nkt) {
            int nb = buf + 2; if (nb >= 3) nb -= 3;
            stage_tiles(sb, nb, t, baseA, baseW, m0, n0, (kt + 2) * TK, h);
        }
        CP_COMMIT();

        const uint32_t bA = sb + SM_A(buf);
        const uint32_t bB = sb + SM_B(buf);
#pragma unroll
        for (int kh = 0; kh < 2; kh++) {
            const int sh = 2 * kh;
            const int sl = 4 + 2 * kh;
            uint32_t ah[4][4], al[4][4];
#pragma unroll
            for (int mf = 0; mf < 4; mf++) {
                int row = wm * 64 + mf * 16 + li + ((sel & 1) ? 8 : 0);
                ldsm4(ah[mf], bA + sw_off(row, sh + ((sel >> 1) & 1)));
                ldsm4(al[mf], bA + sw_off(row, sl + ((sel >> 1) & 1)));
            }
#pragma unroll
            for (int pp = 0; pp < 2; pp++) {
                int brow = wn * 32 + pp * 16 + li + ((sel >> 1) ? 8 : 0);
                uint32_t bh[4], bl[4];
                ldsm4(bh, bB + sw_off(brow, sh + (sel & 1)));
                ldsm4(bl, bB + sw_off(brow, sl + (sel & 1)));
#pragma unroll
                for (int mf = 0; mf < 4; mf++) {
                    mma_bf16(acc[mf][2 * pp],     ah[mf], bh[0], bh[1]);
                    mma_bf16(acc[mf][2 * pp],     ah[mf], bl[0], bl[1]);
                    mma_bf16(acc[mf][2 * pp],     al[mf], bh[0], bh[1]);
                    mma_bf16(acc[mf][2 * pp + 1], ah[mf], bh[2], bh[3]);
                    mma_bf16(acc[mf][2 * pp + 1], ah[mf], bl[2], bl[3]);
                    mma_bf16(acc[mf][2 * pp + 1], al[mf], bh[2], bh[3]);
                }
            }
        }
        if (++buf == 3) buf = 0;
    }

    const int g  = lane >> 2;
    const int tq = lane & 3;
#pragma unroll
    for (int mf = 0; mf < 4; mf++) {
        int r0 = wm * 64 + mf * 16 + g;
        int tokA = s_tok[r0];
        int tokB = s_tok[r0 + 8];
#pragma unroll
        for (int nf = 0; nf < 4; nf++) {
            int col = n0 + wn * 32 + nf * 8 + tq * 2;
            if (tokA >= 0)
                *(float2*)&out[(size_t)tokA * D_OUT + col] =
                    make_float2(acc[mf][nf][0], acc[mf][nf][1]);
            if (tokB >= 0)
                *(float2*)&out[(size_t)tokB * D_OUT + col] =
                    make_float2(acc[mf][nf][2], acc[mf][nf][3]);
        }
    }
}

extern "C" void kernel_launch(void* const* d_in, const int* in_sizes, int n_in,
                              void* d_out, int out_size)
{
    const void*  idx  = d_in[0];
    const float* emb0 = (const float*)d_in[1];
    const float* w0   = (const float*)d_in[2];
    const float* emb1 = (const float*)d_in[3];
    const float* w1   = (const float*)d_in[4];
    const float* emb2 = (const float*)d_in[5];
    const float* w2   = (const float*)d_in[6];
    float* out = (float*)d_out;

    cudaFuncSetAttribute(gemm_mma, cudaFuncAttributeMaxDynamicSharedMemorySize, SM_TOTAL);

    detect_kernel<<<1, 1024>>>((const long long*)idx);
    classify_kernel<<<N_TOK / 256, 256>>>(idx);

    conv_flat<<<1216, 256>>>(emb0, emb1, emb2, w0, w1, w2);

    { dim3 g(N_TOK / TM, D_OUT / TN, 3); gemm_mma<<<g, 256, SM_TOTAL>>>(out); }
}

// round 15
// speedup vs baseline: 3.1725x; 3.0854x over previous
#include <cuda_runtime.h>
#include <cuda_fp16.h>
#include <cstdint>

// AdaptiveEmbedding: 3-cluster gather+projection.
// detect -> classify (warp-aggregated) -> conv_flat (fp32 -> fp16 single
// plane) -> z-grid cp.async 3-stage pipelined mma.sync fp16 GEMM (2 CTAs/SM).
// R15: fp16 single-plane (11 mantissa bits) replaces bf16 3-term split:
// 3x fewer MMAs, 2x less smem crossbar traffic, K-stage 64.
// Baseline-PTX only (harness targets sm_103, no 'a': no tcgen05).

#define N_TOK 16384
#define VOCAB 50257
#define D_OUT 1024
#define TM 128
#define TN 128
#define TK 64

// ---------------- scratch (no allocations allowed) ----------------
__device__ int g_cnt[3];
__device__ int g_is64;
__device__ int g_tok[3 * N_TOK];
__device__ int g_loc[3 * N_TOK];
#define A_ELEMS (16384 * 1344)
#define AB1 ((size_t)16384 * 1024)
#define AB2 ((size_t)16384 * 1280)
__device__ __half g_Ah[A_ELEMS];
#define W_ELEMS (1024 * 1344)
#define WB1 ((size_t)1024 * 1024)
#define WB2 ((size_t)1024 * 1280)
__device__ __half g_Wh[W_ELEMS];

__constant__ int    c_h[3]     = {1024, 256, 64};
__constant__ size_t c_baseA[3] = {0, AB1, AB2};
__constant__ size_t c_baseW[3] = {0, WB1, WB2};

// ---------------- helpers ----------------
__device__ __forceinline__ uint32_t smem_u32(const void* p) {
    uint32_t a;
    asm("{ .reg .u64 t; cvta.to.shared.u64 t, %1; cvt.u32.u64 %0, t; }" : "=r"(a) : "l"(p));
    return a;
}
__device__ __forceinline__ void ldsm4(uint32_t* r, uint32_t addr) {
    asm volatile("ldmatrix.sync.aligned.m8n8.x4.shared.b16 {%0,%1,%2,%3}, [%4];"
                 : "=r"(r[0]), "=r"(r[1]), "=r"(r[2]), "=r"(r[3]) : "r"(addr));
}
__device__ __forceinline__ void mma_f16(float* c, const uint32_t* a, uint32_t b0, uint32_t b1) {
    asm volatile(
        "mma.sync.aligned.m16n8k16.row.col.f32.f16.f16.f32 "
        "{%0,%1,%2,%3}, {%4,%5,%6,%7}, {%8,%9}, {%0,%1,%2,%3};"
        : "+f"(c[0]), "+f"(c[1]), "+f"(c[2]), "+f"(c[3])
        : "r"(a[0]), "r"(a[1]), "r"(a[2]), "r"(a[3]), "r"(b0), "r"(b1));
}
__device__ __forceinline__ void cp16(uint32_t dst, const void* src) {
    asm volatile("cp.async.cg.shared.global [%0], [%1], 16;" :: "r"(dst), "l"(src));
}
#define CP_COMMIT() asm volatile("cp.async.commit_group;" ::: "memory")
#define CP_WAIT1()  asm volatile("cp.async.wait_group 1;" ::: "memory")

// smem tile row = 128B = 8 subs of 16B = 64 halves (one K-stage of 64).
__device__ __forceinline__ uint32_t sw_off(int row, int sub) {
    return (uint32_t)(row * 128 + ((sub ^ (row & 7)) << 4));
}

// ---------------- routing ----------------
__global__ void __launch_bounds__(1024) detect_kernel(const long long* __restrict__ p) {
    __shared__ int bad;
    if (threadIdx.x == 0) bad = 0;
    __syncthreads();
    long long v0 = p[threadIdx.x];
    long long v1 = p[threadIdx.x + 1024];
    long long v2 = p[threadIdx.x + 2048];
    long long v3 = p[threadIdx.x + 3072];
    long long v4 = p[threadIdx.x + 4096];
    long long v5 = p[threadIdx.x + 5120];
    long long v6 = p[threadIdx.x + 6144];
    long long v7 = p[threadIdx.x + 7168];
    bool ok = (v0 >= 0 && v0 < VOCAB) && (v1 >= 0 && v1 < VOCAB) &&
              (v2 >= 0 && v2 < VOCAB) && (v3 >= 0 && v3 < VOCAB) &&
              (v4 >= 0 && v4 < VOCAB) && (v5 >= 0 && v5 < VOCAB) &&
              (v6 >= 0 && v6 < VOCAB) && (v7 >= 0 && v7 < VOCAB);
    if (!ok) bad = 1;
    __syncthreads();
    if (threadIdx.x == 0) {
        g_is64 = (bad == 0);
        g_cnt[0] = 0; g_cnt[1] = 0; g_cnt[2] = 0;
    }
}

__global__ void classify_kernel(const void* __restrict__ idx_raw) {
    int n = blockIdx.x * blockDim.x + threadIdx.x;
    if (n >= N_TOK) return;
    int lane = threadIdx.x & 31;
    int v;
    if (g_is64) v = (int)((const long long*)idx_raw)[n];
    else        v = ((const int*)idx_raw)[n];
    v = min(max(v, 0), VOCAB - 1);
    int c  = (v >= 40000) ? 2 : ((v >= 20000) ? 1 : 0);
    int lo = (c == 2) ? 40000 : ((c == 1) ? 20000 : 0);
    int hicap = (c == 2) ? 10256 : 19999;
    int local = min(v - lo, hicap);
#pragma unroll
    for (int cc = 0; cc < 3; cc++) {
        unsigned m = __ballot_sync(0xFFFFFFFFu, c == cc);
        if (c == cc) {
            int leader = __ffs(m) - 1;
            int base = 0;
            if (lane == leader) base = atomicAdd(&g_cnt[cc], __popc(m));
            base = __shfl_sync(m, base, leader);
            int pos = base + __popc(m & ((1u << lane) - 1u));
            g_tok[cc * N_TOK + pos] = n;
            g_loc[cc * N_TOK + pos] = local;
        }
    }
}

// ---------------- balanced flat fp32 -> fp16 converter ----------------
__device__ __forceinline__ uint4 cvt8(const float* src) {
    float4 v0 = *(const float4*)src;
    float4 v1 = *(const float4*)(src + 4);
    __half2 p0 = __floats2half2_rn(v0.x, v0.y);
    __half2 p1 = __floats2half2_rn(v0.z, v0.w);
    __half2 p2 = __floats2half2_rn(v1.x, v1.y);
    __half2 p3 = __floats2half2_rn(v1.z, v1.w);
    return make_uint4(*(uint32_t*)&p0, *(uint32_t*)&p1,
                      *(uint32_t*)&p2, *(uint32_t*)&p3);
}

// Segments (8-float chunks): 0..2 = gathered A rows per cluster, 3..5 = weights.
__global__ void conv_flat(const float* __restrict__ e0, const float* __restrict__ e1,
                          const float* __restrict__ e2, const float* __restrict__ w0,
                          const float* __restrict__ w1, const float* __restrict__ w2)
{
    const int t0 = g_cnt[0] << 7;
    const int t1 = g_cnt[1] << 5;
    const int t2 = g_cnt[2] << 3;
    const int u0 = D_OUT << 7, u1 = D_OUT << 5, u2 = D_OUT << 3;
    const int e0c = t0, e1c = e0c + t1, e2c = e1c + t2;
    const int e3c = e2c + u0, e4c = e3c + u1, e5c = e4c + u2;
    const int stride = gridDim.x * blockDim.x;

    for (int id = blockIdx.x * blockDim.x + threadIdx.x; id < e5c; id += stride) {
        int z, lid;
        if      (id < e0c) { z = 0; lid = id; }
        else if (id < e1c) { z = 1; lid = id - e0c; }
        else if (id < e2c) { z = 2; lid = id - e1c; }
        else if (id < e3c) { z = 3; lid = id - e2c; }
        else if (id < e4c) { z = 4; lid = id - e3c; }
        else               { z = 5; lid = id - e4c; }
        const bool isA = (z < 3);
        const int cl  = isA ? z : z - 3;
        const int h   = c_h[cl];
        const int lc  = (cl == 0) ? 7 : (cl == 1) ? 5 : 3;
        int s   = lid >> lc;
        int off = (lid & ((1 << lc) - 1)) << 3;
        int srow = isA ? g_loc[cl * N_TOK + s] : s;
        const float* src_mat =
            (z == 0) ? e0 : (z == 1) ? e1 : (z == 2) ? e2 :
            (z == 3) ? w0 : (z == 4) ? w1 : w2;
        uint4 hv = cvt8(src_mat + (size_t)srow * h + off);
        size_t d = (isA ? c_baseA[cl] : c_baseW[cl]) + (size_t)s * h + off;
        if (isA) *(uint4*)&g_Ah[d] = hv;
        else     *(uint4*)&g_Wh[d] = hv;
    }
}

// ---------------- GEMM: fp16, 3-stage pipeline, 2 CTAs/SM ----------------
// Stage sizes unchanged: A 16 KB (128 rows x 64 halves), B 16 KB.
#define SM_TOK 0
#define SM_A(i) (1024 + (i) * 16384)
#define SM_B(i) (50176 + (i) * 16384)
#define SM_TOTAL 99328

__device__ __forceinline__ void stage_tiles(
    uint32_t sb, int buf, int t,
    size_t baseA, size_t baseW, int m0, int n0, int k0, int h)
{
#pragma unroll
    for (int i = 0; i < 4; i++) {
        int cid = t + i * 256;
        int row = cid >> 3, sub = cid & 7;
        const __half* src = g_Ah + baseA + (size_t)(m0 + row) * h + k0 + sub * 8;
        cp16(sb + SM_A(buf) + sw_off(row, sub), src);
    }
#pragma unroll
    for (int i = 0; i < 4; i++) {
        int cid = t + i * 256;
        int row = cid >> 3, sub = cid & 7;
        const __half* src = g_Wh + baseW + (size_t)(n0 + row) * h + k0 + sub * 8;
        cp16(sb + SM_B(buf) + sw_off(row, sub), src);
    }
}

__global__ void __launch_bounds__(256, 2) gemm_mma(float* __restrict__ out)
{
    const int cl  = blockIdx.z;
    const int cnt = g_cnt[cl];
    const int m0  = blockIdx.x * TM;
    if (m0 >= cnt) return;
    const int h     = c_h[cl];
    const size_t baseA = c_baseA[cl];
    const size_t baseW = c_baseW[cl];
    const int n0  = blockIdx.y * TN;

    extern __shared__ __align__(16) char smem[];
    const uint32_t sb = smem_u32(smem);
    int* s_tok = (int*)(smem + SM_TOK);

    const int t    = threadIdx.x;
    const int lane = t & 31;
    const int wid  = t >> 5;
    const int wm   = wid & 1;       // 2 M groups of 64 rows
    const int wn   = wid >> 1;      // 4 N groups of 32 cols
    const int li   = lane & 7;
    const int sel  = lane >> 3;

    if (t < TM) {
        int m = m0 + t;
        s_tok[t] = (m < cnt) ? g_tok[cl * N_TOK + m] : -1;
    }

    const int nkt = h / TK;         // c0:16  c1:4  c2:1
    stage_tiles(sb, 0, t, baseA, baseW, m0, n0, 0, h);
    CP_COMMIT();
    if (nkt > 1) stage_tiles(sb, 1, t, baseA, baseW, m0, n0, TK, h);
    CP_COMMIT();                    // possibly-empty group keeps WAIT1 safe at nkt==1

    float acc[4][4][4];
#pragma unroll
    for (int i = 0; i < 4; i++)
#pragma unroll
        for (int j = 0; j < 4; j++)
#pragma unroll
            for (int q = 0; q < 4; q++) acc[i][j][q] = 0.0f;

    int buf = 0;
    for (int kt = 0; kt < nkt; kt++) {
        CP_WAIT1();          // group kt complete
        __syncthreads();     // all threads finished computing kt-1
        if (kt + 2 < nkt) {
            int nb = buf + 2; if (nb >= 3) nb -= 3;
            stage_tiles(sb, nb, t, baseA, baseW, m0, n0, (kt + 2) * TK, h);
        }
        CP_COMMIT();

        const uint32_t bA = sb + SM_A(buf);
        const uint32_t bB = sb + SM_B(buf);
#pragma unroll
        for (int kh = 0; kh < 4; kh++) {          // 4 x K=16 within the K=64 stage
            const int sh = 2 * kh;                // sub pair {sh, sh+1}
            uint32_t ah[4][4];
#pragma unroll
            for (int mf = 0; mf < 4; mf++) {
                int row = wm * 64 + mf * 16 + li + ((sel & 1) ? 8 : 0);
                ldsm4(ah[mf], bA + sw_off(row, sh + ((sel >> 1) & 1)));
            }
#pragma unroll
            for (int pp = 0; pp < 2; pp++) {
                int brow = wn * 32 + pp * 16 + li + ((sel >> 1) ? 8 : 0);
                uint32_t bh[4];
                ldsm4(bh, bB + sw_off(brow, sh + (sel & 1)));
#pragma unroll
                for (int mf = 0; mf < 4; mf++) {
                    mma_f16(acc[mf][2 * pp],     ah[mf], bh[0], bh[1]);
                    mma_f16(acc[mf][2 * pp + 1], ah[mf], bh[2], bh[3]);
                }
            }
        }
        if (++buf == 3) buf = 0;
    }

    const int g  = lane >> 2;
    const int tq = lane & 3;
#pragma unroll
    for (int mf = 0; mf < 4; mf++) {
        int r0 = wm * 64 + mf * 16 + g;
        int tokA = s_tok[r0];
        int tokB = s_tok[r0 + 8];
#pragma unroll
        for (int nf = 0; nf < 4; nf++) {
            int col = n0 + wn * 32 + nf * 8 + tq * 2;
            if (tokA >= 0)
                *(float2*)&out[(size_t)tokA * D_OUT + col] =
                    make_float2(acc[mf][nf][0], acc[mf][nf][1]);
            if (tokB >= 0)
                *(float2*)&out[(size_t)tokB * D_OUT + col] =
                    make_float2(acc[mf][nf][2], acc[mf][nf][3]);
        }
    }
}

extern "C" void kernel_launch(void* const* d_in, const int* in_sizes, int n_in,
                              void* d_out, int out_size)
{
    const void*  idx  = d_in[0];
    const float* emb0 = (const float*)d_in[1];
    const float* w0   = (const float*)d_in[2];
    const float* emb1 = (const float*)d_in[3];
    const float* w1   = (const float*)d_in[4];
    const float* emb2 = (const float*)d_in[5];
    const float* w2   = (const float*)d_in[6];
    float* out = (float*)d_out;

    cudaFuncSetAttribute(gemm_mma, cudaFuncAttributeMaxDynamicSharedMemorySize, SM_TOTAL);

    detect_kernel<<<1, 1024>>>((const long long*)idx);
    classify_kernel<<<N_TOK / 256, 256>>>(idx);

    conv_flat<<<1216, 256>>>(emb0, emb1, emb2, w0, w1, w2);

    { dim3 g(N_TOK / TM, D_OUT / TN, 3); gemm_mma<<<g, 256, SM_TOTAL>>>(out); }
}

// round 17
// speedup vs baseline: 3.2101x; 1.0118x over previous
#include <cuda_runtime.h>
#include <cuda_fp16.h>
#include <cstdint>

// AdaptiveEmbedding: 3-cluster gather+projection.
// memset counts -> classify (inline dtype detect + warp-aggregated compaction)
// -> conv_flat (fp32 -> fp16) -> z-grid cp.async 3-stage pipelined mma.sync
// fp16 GEMM (2 CTAs/SM).  GEMM frozen from R15 (validated: 55.6us, 2.93e-4).
// Baseline-PTX only (harness targets sm_103, no 'a': no tcgen05).

#define N_TOK 16384
#define VOCAB 50257
#define D_OUT 1024
#define TM 128
#define TN 128
#define TK 64

// ---------------- scratch (no allocations allowed) ----------------
__device__ int g_cnt[3];
__device__ int g_tok[3 * N_TOK];
__device__ int g_loc[3 * N_TOK];
#define A_ELEMS (16384 * 1344)
#define AB1 ((size_t)16384 * 1024)
#define AB2 ((size_t)16384 * 1280)
__device__ __half g_Ah[A_ELEMS];
#define W_ELEMS (1024 * 1344)
#define WB1 ((size_t)1024 * 1024)
#define WB2 ((size_t)1024 * 1280)
__device__ __half g_Wh[W_ELEMS];

__constant__ int    c_h[3]     = {1024, 256, 64};
__constant__ size_t c_baseA[3] = {0, AB1, AB2};
__constant__ size_t c_baseW[3] = {0, WB1, WB2};

// ---------------- helpers ----------------
__device__ __forceinline__ uint32_t smem_u32(const void* p) {
    uint32_t a;
    asm("{ .reg .u64 t; cvta.to.shared.u64 t, %1; cvt.u32.u64 %0, t; }" : "=r"(a) : "l"(p));
    return a;
}
__device__ __forceinline__ void ldsm4(uint32_t* r, uint32_t addr) {
    asm volatile("ldmatrix.sync.aligned.m8n8.x4.shared.b16 {%0,%1,%2,%3}, [%4];"
                 : "=r"(r[0]), "=r"(r[1]), "=r"(r[2]), "=r"(r[3]) : "r"(addr));
}
__device__ __forceinline__ void mma_f16(float* c, const uint32_t* a, uint32_t b0, uint32_t b1) {
    asm volatile(
        "mma.sync.aligned.m16n8k16.row.col.f32.f16.f16.f32 "
        "{%0,%1,%2,%3}, {%4,%5,%6,%7}, {%8,%9}, {%0,%1,%2,%3};"
        : "+f"(c[0]), "+f"(c[1]), "+f"(c[2]), "+f"(c[3])
        : "r"(a[0]), "r"(a[1]), "r"(a[2]), "r"(a[3]), "r"(b0), "r"(b1));
}
__device__ __forceinline__ void cp16(uint32_t dst, const void* src) {
    asm volatile("cp.async.cg.shared.global [%0], [%1], 16;" :: "r"(dst), "l"(src));
}
#define CP_COMMIT() asm volatile("cp.async.commit_group;" ::: "memory")
#define CP_WAIT1()  asm volatile("cp.async.wait_group 1;" ::: "memory")

// smem tile row = 128B = 8 subs of 16B = 64 halves (one K-stage of 64).
__device__ __forceinline__ uint32_t sw_off(int row, int sub) {
    return (uint32_t)(row * 128 + ((sub ^ (row & 7)) << 4));
}

// ---------------- classify (with inline dtype detection) ----------------
__global__ void __launch_bounds__(256) classify_kernel(const void* __restrict__ idx_raw) {
    // dtype vote: first 256 values as int64 (2KB — in-bounds either way, L2-hot).
    // int32 data aliased as int64 is valid with prob ~2e-5 per element; all-256
    // valid => genuinely int64. Every block computes the same verdict.
    bool okv;
    {
        long long v = ((const long long*)idx_raw)[threadIdx.x];
        okv = (v >= 0 && v < VOCAB);
    }
    const int is64 = __syncthreads_and((int)okv);

    int n = blockIdx.x * blockDim.x + threadIdx.x;
    if (n >= N_TOK) return;
    int lane = threadIdx.x & 31;
    int v;
    if (is64) v = (int)((const long long*)idx_raw)[n];
    else      v = ((const int*)idx_raw)[n];
    v = min(max(v, 0), VOCAB - 1);
    int c  = (v >= 40000) ? 2 : ((v >= 20000) ? 1 : 0);
    int lo = (c == 2) ? 40000 : ((c == 1) ? 20000 : 0);
    int hicap = (c == 2) ? 10256 : 19999;
    int local = min(v - lo, hicap);
#pragma unroll
    for (int cc = 0; cc < 3; cc++) {
        unsigned m = __ballot_sync(0xFFFFFFFFu, c == cc);
        if (c == cc) {
            int leader = __ffs(m) - 1;
            int base = 0;
            if (lane == leader) base = atomicAdd(&g_cnt[cc], __popc(m));
            base = __shfl_sync(m, base, leader);
            int pos = base + __popc(m & ((1u << lane) - 1u));
            g_tok[cc * N_TOK + pos] = n;
            g_loc[cc * N_TOK + pos] = local;
        }
    }
}

// ---------------- balanced flat fp32 -> fp16 converter ----------------
__device__ __forceinline__ uint4 cvt8(const float* src) {
    float4 v0 = *(const float4*)src;
    float4 v1 = *(const float4*)(src + 4);
    __half2 p0 = __floats2half2_rn(v0.x, v0.y);
    __half2 p1 = __floats2half2_rn(v0.z, v0.w);
    __half2 p2 = __floats2half2_rn(v1.x, v1.y);
    __half2 p3 = __floats2half2_rn(v1.z, v1.w);
    return make_uint4(*(uint32_t*)&p0, *(uint32_t*)&p1,
                      *(uint32_t*)&p2, *(uint32_t*)&p3);
}

// Segments (8-float chunks): 0..2 = gathered A rows per cluster, 3..5 = weights.
__global__ void conv_flat(const float* __restrict__ e0, const float* __restrict__ e1,
                          const float* __restrict__ e2, const float* __restrict__ w0,
                          const float* __restrict__ w1, const float* __restrict__ w2)
{
    const int t0 = g_cnt[0] << 7;
    const int t1 = g_cnt[1] << 5;
    const int t2 = g_cnt[2] << 3;
    const int u0 = D_OUT << 7, u1 = D_OUT << 5, u2 = D_OUT << 3;
    const int e0c = t0, e1c = e0c + t1, e2c = e1c + t2;
    const int e3c = e2c + u0, e4c = e3c + u1, e5c = e4c + u2;
    const int stride = gridDim.x * blockDim.x;

    for (int id = blockIdx.x * blockDim.x + threadIdx.x; id < e5c; id += stride) {
        int z, lid;
        if      (id < e0c) { z = 0; lid = id; }
        else if (id < e1c) { z = 1; lid = id - e0c; }
        else if (id < e2c) { z = 2; lid = id - e1c; }
        else if (id < e3c) { z = 3; lid = id - e2c; }
        else if (id < e4c) { z = 4; lid = id - e3c; }
        else               { z = 5; lid = id - e4c; }
        const bool isA = (z < 3);
        const int cl  = isA ? z : z - 3;
        const int h   = c_h[cl];
        const int lc  = (cl == 0) ? 7 : (cl == 1) ? 5 : 3;
        int s   = lid >> lc;
        int off = (lid & ((1 << lc) - 1)) << 3;
        int srow = isA ? g_loc[cl * N_TOK + s] : s;
        const float* src_mat =
            (z == 0) ? e0 : (z == 1) ? e1 : (z == 2) ? e2 :
            (z == 3) ? w0 : (z == 4) ? w1 : w2;
        uint4 hv = cvt8(src_mat + (size_t)srow * h + off);
        size_t d = (isA ? c_baseA[cl] : c_baseW[cl]) + (size_t)s * h + off;
        if (isA) *(uint4*)&g_Ah[d] = hv;
        else     *(uint4*)&g_Wh[d] = hv;
    }
}

// ---------------- GEMM: fp16, 3-stage pipeline, 2 CTAs/SM (frozen) ----------------
#define SM_TOK 0
#define SM_A(i) (1024 + (i) * 16384)
#define SM_B(i) (50176 + (i) * 16384)
#define SM_TOTAL 99328

__device__ __forceinline__ void stage_tiles(
    uint32_t sb, int buf, int t,
    size_t baseA, size_t baseW, int m0, int n0, int k0, int h)
{
#pragma unroll
    for (int i = 0; i < 4; i++) {
        int cid = t + i * 256;
        int row = cid >> 3, sub = cid & 7;
        const __half* src = g_Ah + baseA + (size_t)(m0 + row) * h + k0 + sub * 8;
        cp16(sb + SM_A(buf) + sw_off(row, sub), src);
    }
#pragma unroll
    for (int i = 0; i < 4; i++) {
        int cid = t + i * 256;
        int row = cid >> 3, sub = cid & 7;
        const __half* src = g_Wh + baseW + (size_t)(n0 + row) * h + k0 + sub * 8;
        cp16(sb + SM_B(buf) + sw_off(row, sub), src);
    }
}

__global__ void __launch_bounds__(256, 2) gemm_mma(float* __restrict__ out)
{
    const int cl  = blockIdx.z;
    const int cnt = g_cnt[cl];
    const int m0  = blockIdx.x * TM;
    if (m0 >= cnt) return;
    const int h     = c_h[cl];
    const size_t baseA = c_baseA[cl];
    const size_t baseW = c_baseW[cl];
    const int n0  = blockIdx.y * TN;

    extern __shared__ __align__(16) char smem[];
    const uint32_t sb = smem_u32(smem);
    int* s_tok = (int*)(smem + SM_TOK);

    const int t    = threadIdx.x;
    const int lane = t & 31;
    const int wid  = t >> 5;
    const int wm   = wid & 1;       // 2 M groups of 64 rows
    const int wn   = wid >> 1;      // 4 N groups of 32 cols
    const int li   = lane & 7;
    const int sel  = lane >> 3;

    if (t < TM) {
        int m = m0 + t;
        s_tok[t] = (m < cnt) ? g_tok[cl * N_TOK + m] : -1;
    }

    const int nkt = h / TK;         // c0:16  c1:4  c2:1
    stage_tiles(sb, 0, t, baseA, baseW, m0, n0, 0, h);
    CP_COMMIT();
    if (nkt > 1) stage_tiles(sb, 1, t, baseA, baseW, m0, n0, TK, h);
    CP_COMMIT();                    // possibly-empty group keeps WAIT1 safe at nkt==1

    float acc[4][4][4];
#pragma unroll
    for (int i = 0; i < 4; i++)
#pragma unroll
        for (int j = 0; j < 4; j++)
#pragma unroll
            for (int q = 0; q < 4; q++) acc[i][j][q] = 0.0f;

    int buf = 0;
    for (int kt = 0; kt < nkt; kt++) {
        CP_WAIT1();          // group kt complete
        __syncthreads();     // all threads finished computing kt-1
        if (kt + 2 < nkt) {
            int nb = buf + 2; if (nb >= 3) nb -= 3;
            stage_tiles(sb, nb, t, baseA, baseW, m0, n0, (kt + 2) * TK, h);
        }
        CP_COMMIT();

        const uint32_t bA = sb + SM_A(buf);
        const uint32_t bB = sb + SM_B(buf);
#pragma unroll
        for (int kh = 0; kh < 4; kh++) {          // 4 x K=16 within the K=64 stage
            const int sh = 2 * kh;                // sub pair {sh, sh+1}
            uint32_t ah[4][4];
#pragma unroll
            for (int mf = 0; mf < 4; mf++) {
                int row = wm * 64 + mf * 16 + li + ((sel & 1) ? 8 : 0);
                ldsm4(ah[mf], bA + sw_off(row, sh + ((sel >> 1) & 1)));
            }
#pragma unroll
            for (int pp = 0; pp < 2; pp++) {
                int brow = wn * 32 + pp * 16 + li + ((sel >> 1) ? 8 : 0);
                uint32_t bh[4];
                ldsm4(bh, bB + sw_off(brow, sh + (sel & 1)));
#pragma unroll
                for (int mf = 0; mf < 4; mf++) {
                    mma_f16(acc[mf][2 * pp],     ah[mf], bh[0], bh[1]);
                    mma_f16(acc[mf][2 * pp + 1], ah[mf], bh[2], bh[3]);
                }
            }
        }
        if (++buf == 3) buf = 0;
    }

    const int g  = lane >> 2;
    const int tq = lane & 3;
#pragma unroll
    for (int mf = 0; mf < 4; mf++) {
        int r0 = wm * 64 + mf * 16 + g;
        int tokA = s_tok[r0];
        int tokB = s_tok[r0 + 8];
#pragma unroll
        for (int nf = 0; nf < 4; nf++) {
            int col = n0 + wn * 32 + nf * 8 + tq * 2;
            if (tokA >= 0)
                *(float2*)&out[(size_t)tokA * D_OUT + col] =
                    make_float2(acc[mf][nf][0], acc[mf][nf][1]);
            if (tokB >= 0)
                *(float2*)&out[(size_t)tokB * D_OUT + col] =
                    make_float2(acc[mf][nf][2], acc[mf][nf][3]);
        }
    }
}

extern "C" void kernel_launch(void* const* d_in, const int* in_sizes, int n_in,
                              void* d_out, int out_size)
{
    const void*  idx  = d_in[0];
    const float* emb0 = (const float*)d_in[1];
    const float* w0   = (const float*)d_in[2];
    const float* emb1 = (const float*)d_in[3];
    const float* w1   = (const float*)d_in[4];
    const float* emb2 = (const float*)d_in[5];
    const float* w2   = (const float*)d_in[6];
    float* out = (float*)d_out;

    cudaFuncSetAttribute(gemm_mma, cudaFuncAttributeMaxDynamicSharedMemorySize, SM_TOTAL);

    // zero the per-cluster counters via a graph memset node (no kernel launch)
    void* cnt_ptr = nullptr;
    cudaGetSymbolAddress(&cnt_ptr, g_cnt);
    cudaMemsetAsync(cnt_ptr, 0, 3 * sizeof(int));

    classify_kernel<<<N_TOK / 256, 256>>>(idx);

    conv_flat<<<1216, 256>>>(emb0, emb1, emb2, w0, w1, w2);

    { dim3 g(N_TOK / TM, D_OUT / TN, 3); gemm_mma<<<g, 256, SM_TOTAL>>>(out); }
}